// round 1
// baseline (speedup 1.0000x reference)
#include <cuda_runtime.h>

#define SQH 0.70710678118654752440f

// Precomputed circuit unitary columns and measurement matrices (device scratch,
// no allocation). g_U[k][j] = U[k][j] (complex as float2).
// g_A[s][t] = {A0, A1} with off-diagonal entries pre-doubled (symmetric fold).
__device__ float2 g_U[32][32];
__device__ float2 g_A[32][32];

// ---------------- gate helpers on a per-thread 32-amp register state -------
// Qubit w lives at bit position P = 4 - w (qubit 0 most significant).

template<int P>
__device__ __forceinline__ void g_rz(float* sr, float* si, float c, float s) {
#pragma unroll
    for (int k = 0; k < 32; k++) {
        float r = sr[k], i = si[k];
        if (((k >> P) & 1) == 0) {      // amp *= (c - i s)
            sr[k] = fmaf(s, i, c * r);
            si[k] = fmaf(-s, r, c * i);
        } else {                          // amp *= (c + i s)
            sr[k] = fmaf(-s, i, c * r);
            si[k] = fmaf(s, r, c * i);
        }
    }
}

template<int P>
__device__ __forceinline__ void g_rx(float* sr, float* si, float c, float sn) {
    // [[c, -i sn], [-i sn, c]]
#pragma unroll
    for (int k = 0; k < 32; k++) {
        if (((k >> P) & 1) == 0) {
            int p = k | (1 << P);
            float a0r = sr[k], a0i = si[k], a1r = sr[p], a1i = si[p];
            sr[k] = fmaf(sn, a1i, c * a0r);
            si[k] = fmaf(-sn, a1r, c * a0i);
            sr[p] = fmaf(sn, a0i, c * a1r);
            si[p] = fmaf(-sn, a0r, c * a1i);
        }
    }
}

template<int P>
__device__ __forceinline__ void g_ry(float* sr, float* si, float c, float sn) {
    // [[c, -sn], [sn, c]] (real)
#pragma unroll
    for (int k = 0; k < 32; k++) {
        if (((k >> P) & 1) == 0) {
            int p = k | (1 << P);
            float a0r = sr[k], a0i = si[k], a1r = sr[p], a1i = si[p];
            sr[k] = fmaf(-sn, a1r, c * a0r);
            si[k] = fmaf(-sn, a1i, c * a0i);
            sr[p] = fmaf(sn, a0r, c * a1r);
            si[p] = fmaf(sn, a0i, c * a1i);
        }
    }
}

template<int PC, int PT>
__device__ __forceinline__ void g_cnot(float* sr, float* si) {
#pragma unroll
    for (int k = 0; k < 32; k++) {
        if ((((k >> PC) & 1) == 1) && (((k >> PT) & 1) == 0)) {
            int p = k | (1 << PT);
            float tr = sr[k]; sr[k] = sr[p]; sr[p] = tr;
            float ti = si[k]; si[k] = si[p]; si[p] = ti;
        }
    }
}

template<int PA, int PB>
__device__ __forceinline__ void g_cz(float* sr, float* si) {
#pragma unroll
    for (int k = 0; k < 32; k++) {
        if ((((k >> PA) & 1) == 1) && (((k >> PB) & 1) == 1)) {
            sr[k] = -sr[k];
            si[k] = -si[k];
        }
    }
}

template<int PC, int PT>
__device__ __forceinline__ void g_cry(float* sr, float* si, float c, float sn) {
#pragma unroll
    for (int k = 0; k < 32; k++) {
        if ((((k >> PC) & 1) == 1) && (((k >> PT) & 1) == 0)) {
            int p = k | (1 << PT);
            float a0r = sr[k], a0i = si[k], a1r = sr[p], a1i = si[p];
            sr[k] = fmaf(-sn, a1r, c * a0r);
            si[k] = fmaf(-sn, a1i, c * a0i);
            sr[p] = fmaf(sn, a0r, c * a1r);
            si[p] = fmaf(sn, a0i, c * a1i);
        }
    }
}

template<int PC, int PT>
__device__ __forceinline__ void g_crx(float* sr, float* si, float c, float sn) {
#pragma unroll
    for (int k = 0; k < 32; k++) {
        if ((((k >> PC) & 1) == 1) && (((k >> PT) & 1) == 0)) {
            int p = k | (1 << PT);
            float a0r = sr[k], a0i = si[k], a1r = sr[p], a1i = si[p];
            sr[k] = fmaf(sn, a1i, c * a0r);
            si[k] = fmaf(-sn, a1r, c * a0i);
            sr[p] = fmaf(sn, a0i, c * a1r);
            si[p] = fmaf(-sn, a0r, c * a1i);
        }
    }
}

// One conv_block iteration on wire pair (a, b) -> bit positions (PA, PB).
template<int PA, int PB>
__device__ __forceinline__ void conv_iter(float* sr, float* si, float t1, float t2) {
    float c1, s1, c2, s2;
    sincosf(0.5f * t1, &s1, &c1);
    sincosf(0.5f * t2, &s2, &c2);
    g_cnot<PA, PB>(sr, si);
    g_rz<PB>(sr, si, c1, s1);
    g_cnot<PA, PB>(sr, si);
    g_rx<PA>(sr, si, SQH, SQH);   // RX(+pi/2)
    g_rx<PB>(sr, si, SQH, SQH);
    g_cnot<PA, PB>(sr, si);
    g_rx<PA>(sr, si, SQH, -SQH);  // RX(-pi/2)
    g_rx<PB>(sr, si, SQH, -SQH);
    g_cz<PA, PB>(sr, si);
    g_rz<PB>(sr, si, c2, s2);
    g_cz<PA, PB>(sr, si);
}

// pool_block on wires (a, b) -> bit positions (PA, PB).
template<int PA, int PB>
__device__ __forceinline__ void pool_blk(float* sr, float* si, float w0, float w1) {
    float c0, s0, c1, s1;
    sincosf(0.5f * w0, &s0, &c0);
    sincosf(0.5f * w1, &s1, &c1);
    g_ry<PA>(sr, si, c0, s0);
    g_ry<PB>(sr, si, c1, s1);
    g_cnot<PA, PB>(sr, si);        // CNOT(a, b)
    g_cry<PB, PA>(sr, si, c0, s0); // CRY: control b, target a
    g_crx<PA, PB>(sr, si, c1, s1); // CRX: control a, target b
    g_cnot<PB, PA>(sr, si);        // CNOT(b, a)
}

// ---------------- kernel 1: simulate the 32 basis columns of U -------------
__global__ void __launch_bounds__(32) sim_kernel(const float* __restrict__ conv,
                                                 const float* __restrict__ pool) {
    int j = threadIdx.x;  // column index
    float sr[32], si[32];
#pragma unroll
    for (int k = 0; k < 32; k++) { sr[k] = (k == j) ? 1.0f : 0.0f; si[k] = 0.0f; }

    // Layer 0: wires [0,1,2,3,4]; pos(w) = 4 - w
    conv_iter<4, 3>(sr, si, conv[0], conv[2]);   // (0,1)
    conv_iter<3, 2>(sr, si, conv[1], conv[3]);   // (1,2)
    conv_iter<2, 1>(sr, si, conv[2], conv[4]);   // (2,3)
    conv_iter<1, 0>(sr, si, conv[3], conv[5]);   // (3,4)
    conv_iter<0, 4>(sr, si, conv[4], conv[6]);   // (4,0)
    pool_blk<4, 3>(sr, si, pool[0], pool[1]);    // wires (0,1)

    // Layer 1: wires [1,2,3,4]
    conv_iter<3, 2>(sr, si, conv[15 + 0], conv[15 + 2]);  // (1,2)
    conv_iter<2, 1>(sr, si, conv[15 + 1], conv[15 + 3]);  // (2,3)
    conv_iter<1, 0>(sr, si, conv[15 + 2], conv[15 + 4]);  // (3,4)
    conv_iter<0, 3>(sr, si, conv[15 + 3], conv[15 + 5]);  // (4,1)
    pool_blk<3, 2>(sr, si, pool[2], pool[3]);    // wires (1,2)

#pragma unroll
    for (int k = 0; k < 32; k++) g_U[k][j] = make_float2(sr[k], si[k]);
}

// ---------------- kernel 2: A_c = sum_k fc_w[c,k] * Re(U^T D_wk U) ---------
// Measured wires: 2 (bit 2) and 3 (bit 1).
__global__ void __launch_bounds__(1024) amat_kernel(const float* __restrict__ fcw) {
    __shared__ float2 u[32][32];
    int tid = threadIdx.x;
    if (tid < 512) {
        ((float4*)u)[tid] = ((const float4*)g_U)[tid];
    }
    __syncthreads();

    int s = tid >> 5;
    int j = tid & 31;
    float m2 = 0.0f, m3 = 0.0f;
#pragma unroll
    for (int k = 0; k < 32; k++) {
        float2 us = u[k][s];
        float2 uj = u[k][j];
        float pr = us.x * uj.x + us.y * uj.y;  // Re(conj(U_ks) * U_kj)
        m2 += ((k >> 2) & 1) ? -pr : pr;       // D for wire 2
        m3 += ((k >> 1) & 1) ? -pr : pr;       // D for wire 3
    }
    float a0 = fcw[0] * m2 + fcw[1] * m3;
    float a1 = fcw[2] * m2 + fcw[3] * m3;
    float sc = (s == j) ? 1.0f : 2.0f;         // fold symmetry: double off-diag
    g_A[s][j] = make_float2(sc * a0, sc * a1);
}

// ---------------- kernel 3: per-batch quadratic forms ----------------------
__global__ void __launch_bounds__(256) qcnn_main(const float* __restrict__ x,
                                                 const float* __restrict__ fcb,
                                                 float* __restrict__ out, int B) {
    __shared__ float2 sA[32][32];
    {
        const float4* src = (const float4*)g_A;
        float4* dst = (float4*)sA;
#pragma unroll
        for (int i = threadIdx.x; i < 512; i += 256) dst[i] = src[i];
    }
    __syncthreads();

    int b = blockIdx.x * 256 + threadIdx.x;
    if (b >= B) return;

    float cc[5], ssn[5];
#pragma unroll
    for (int q = 0; q < 5; q++) {
        float xv = x[b * 5 + q];
        sincosf(0.5f * xv, &ssn[q], &cc[q]);
    }

    // psi[s], s = b0*16 + b1*8 + b2*4 + b3*2 + b4 (bq=0 -> cos, 1 -> sin)
    float t01[4], t34[4], t234[8], psi[32];
    t01[0] = cc[0] * cc[1]; t01[1] = cc[0] * ssn[1];
    t01[2] = ssn[0] * cc[1]; t01[3] = ssn[0] * ssn[1];
    t34[0] = cc[3] * cc[4]; t34[1] = cc[3] * ssn[4];
    t34[2] = ssn[3] * cc[4]; t34[3] = ssn[3] * ssn[4];
#pragma unroll
    for (int i = 0; i < 4; i++) {
        t234[i]     = cc[2]  * t34[i];
        t234[4 + i] = ssn[2] * t34[i];
    }
#pragma unroll
    for (int s = 0; s < 32; s++) psi[s] = t01[s >> 3] * t234[s & 7];

    // out_c = sum_{s<=t} A'_c[s][t] psi_s psi_t  (off-diag pre-doubled)
    float acc0 = 0.0f, acc1 = 0.0f;
#pragma unroll
    for (int s = 0; s < 32; s++) {
        float d0 = 0.0f, d1 = 0.0f;
#pragma unroll
        for (int t = s; t < 32; t++) {
            float2 a = sA[s][t];
            d0 = fmaf(a.x, psi[t], d0);
            d1 = fmaf(a.y, psi[t], d1);
        }
        acc0 = fmaf(psi[s], d0, acc0);
        acc1 = fmaf(psi[s], d1, acc1);
    }
    out[2 * b + 0] = acc0 + fcb[0];
    out[2 * b + 1] = acc1 + fcb[1];
}

extern "C" void kernel_launch(void* const* d_in, const int* in_sizes, int n_in,
                              void* d_out, int out_size) {
    const float* x    = (const float*)d_in[0];  // (B, 5)
    const float* conv = (const float*)d_in[1];  // (2, 15)
    const float* pool = (const float*)d_in[2];  // (2, 2)
    const float* fcw  = (const float*)d_in[3];  // (2, 2)
    const float* fcb  = (const float*)d_in[4];  // (2,)
    float* out = (float*)d_out;

    int B = in_sizes[0] / 5;
    sim_kernel<<<1, 32>>>(conv, pool);
    amat_kernel<<<1, 1024>>>(fcw);
    int blocks = (B + 255) / 256;
    qcnn_main<<<blocks, 256>>>(x, fcb, out, B);
}

// round 2
// speedup vs baseline: 1.9911x; 1.9911x over previous
#include <cuda_runtime.h>

#define SQH 0.70710678118654752440f
typedef unsigned long long u64;

// Device scratch (no allocation): U columns, and the 243-coeff tensor
// T[e4*81+e3*27+e2*9+e1*3+e0] (float2 = the two output classes), where e_P
// indexes the basis {1, cos x_q, sin x_q} for the qubit at bit position P=4-q.
__device__ float2 g_U[32][32];
__device__ float2 g_T[243];

// ---------------- f32x2 packed-FMA helpers ---------------------------------
__device__ __forceinline__ u64 pk(float v) {
    u64 r; asm("mov.b64 %0, {%1,%1};" : "=l"(r) : "f"(v)); return r;
}
__device__ __forceinline__ u64 f2fma(u64 a, u64 b, u64 c) {
    u64 d; asm("fma.rn.f32x2 %0, %1, %2, %3;" : "=l"(d) : "l"(a), "l"(b), "l"(c));
    return d;
}

// ---------------- warp-level gates: lane l holds amplitude index l ---------
template<int P>
__device__ __forceinline__ void w_rz(int l, float& ar, float& ai, float c, float s) {
    float t = ((l >> P) & 1) ? -s : s;
    float r = ar, i = ai;
    ar = fmaf(t, i, c * r);
    ai = fmaf(-t, r, c * i);
}
template<int P>
__device__ __forceinline__ void w_rx(int l, float& ar, float& ai, float c, float sn) {
    float pr = __shfl_xor_sync(0xffffffffu, ar, 1 << P);
    float pi = __shfl_xor_sync(0xffffffffu, ai, 1 << P);
    float r = ar, i = ai;
    ar = fmaf(sn, pi, c * r);
    ai = fmaf(-sn, pr, c * i);
}
template<int P>
__device__ __forceinline__ void w_ry(int l, float& ar, float& ai, float c, float sn) {
    float pr = __shfl_xor_sync(0xffffffffu, ar, 1 << P);
    float pi = __shfl_xor_sync(0xffffffffu, ai, 1 << P);
    float sg = ((l >> P) & 1) ? sn : -sn;
    ar = fmaf(sg, pr, c * ar);
    ai = fmaf(sg, pi, c * ai);
}
template<int PC, int PT>
__device__ __forceinline__ void w_cnot(int l, float& ar, float& ai) {
    float pr = __shfl_xor_sync(0xffffffffu, ar, 1 << PT);
    float pi = __shfl_xor_sync(0xffffffffu, ai, 1 << PT);
    if ((l >> PC) & 1) { ar = pr; ai = pi; }
}
template<int PA, int PB>
__device__ __forceinline__ void w_cz(int l, float& ar, float& ai) {
    if (((l >> PA) & 1) && ((l >> PB) & 1)) { ar = -ar; ai = -ai; }
}
template<int PC, int PT>
__device__ __forceinline__ void w_cry(int l, float& ar, float& ai, float c, float sn) {
    float pr = __shfl_xor_sync(0xffffffffu, ar, 1 << PT);
    float pi = __shfl_xor_sync(0xffffffffu, ai, 1 << PT);
    if ((l >> PC) & 1) {
        float sg = ((l >> PT) & 1) ? sn : -sn;
        ar = fmaf(sg, pr, c * ar);
        ai = fmaf(sg, pi, c * ai);
    }
}
template<int PC, int PT>
__device__ __forceinline__ void w_crx(int l, float& ar, float& ai, float c, float sn) {
    float pr = __shfl_xor_sync(0xffffffffu, ar, 1 << PT);
    float pi = __shfl_xor_sync(0xffffffffu, ai, 1 << PT);
    if ((l >> PC) & 1) {
        float r = ar, i = ai;
        ar = fmaf(sn, pi, c * r);
        ai = fmaf(-sn, pr, c * i);
    }
}

template<int PA, int PB>
__device__ __forceinline__ void conv_iter(int l, float& ar, float& ai, float t1, float t2) {
    float c1, s1, c2, s2;
    sincosf(0.5f * t1, &s1, &c1);
    sincosf(0.5f * t2, &s2, &c2);
    w_cnot<PA, PB>(l, ar, ai);
    w_rz<PB>(l, ar, ai, c1, s1);
    w_cnot<PA, PB>(l, ar, ai);
    w_rx<PA>(l, ar, ai, SQH, SQH);
    w_rx<PB>(l, ar, ai, SQH, SQH);
    w_cnot<PA, PB>(l, ar, ai);
    w_rx<PA>(l, ar, ai, SQH, -SQH);
    w_rx<PB>(l, ar, ai, SQH, -SQH);
    w_cz<PA, PB>(l, ar, ai);
    w_rz<PB>(l, ar, ai, c2, s2);
    w_cz<PA, PB>(l, ar, ai);
}

template<int PA, int PB>
__device__ __forceinline__ void pool_blk(int l, float& ar, float& ai, float w0, float w1) {
    float c0, s0, c1, s1;
    sincosf(0.5f * w0, &s0, &c0);
    sincosf(0.5f * w1, &s1, &c1);
    w_ry<PA>(l, ar, ai, c0, s0);
    w_ry<PB>(l, ar, ai, c1, s1);
    w_cnot<PA, PB>(l, ar, ai);
    w_cry<PB, PA>(l, ar, ai, c0, s0);
    w_crx<PA, PB>(l, ar, ai, c1, s1);
    w_cnot<PB, PA>(l, ar, ai);
}

// ---------------- kernel 1: U columns, one warp per column -----------------
__global__ void __launch_bounds__(32) sim_kernel(const float* __restrict__ conv,
                                                 const float* __restrict__ pool) {
    int j = blockIdx.x;   // column
    int l = threadIdx.x;  // amplitude
    float ar = (l == j) ? 1.0f : 0.0f, ai = 0.0f;

    // Layer 0: wires [0..4], pos(w) = 4 - w
    conv_iter<4, 3>(l, ar, ai, conv[0], conv[2]);
    conv_iter<3, 2>(l, ar, ai, conv[1], conv[3]);
    conv_iter<2, 1>(l, ar, ai, conv[2], conv[4]);
    conv_iter<1, 0>(l, ar, ai, conv[3], conv[5]);
    conv_iter<0, 4>(l, ar, ai, conv[4], conv[6]);
    pool_blk<4, 3>(l, ar, ai, pool[0], pool[1]);

    // Layer 1: wires [1..4]
    conv_iter<3, 2>(l, ar, ai, conv[15 + 0], conv[15 + 2]);
    conv_iter<2, 1>(l, ar, ai, conv[15 + 1], conv[15 + 3]);
    conv_iter<1, 0>(l, ar, ai, conv[15 + 2], conv[15 + 4]);
    conv_iter<0, 3>(l, ar, ai, conv[15 + 3], conv[15 + 5]);
    pool_blk<3, 2>(l, ar, ai, pool[2], pool[3]);

    g_U[l][j] = make_float2(ar, ai);
}

// ---------------- kernel 2: A matrices -> 243-coeff cosine/sine tensor -----
__device__ __forceinline__ void mode_xform(const float2* __restrict__ In,
                                           float2* __restrict__ Out, int S) {
    // In size 4*S (digit d at stride S), Out size 3*S: Out[rest*3+e]
    //   e=0 (basis 1):   0.5*(In[rest] + In[3S+rest])
    //   e=1 (basis cos): 0.5*(In[rest] - In[3S+rest])
    //   e=2 (basis sin): 0.5*(In[S+rest] + In[2S+rest])
    for (int idx = threadIdx.x; idx < 3 * S; idx += 1024) {
        int rest = idx / 3, e = idx - rest * 3;
        float2 a, b, o;
        if (e == 2) { a = In[S + rest]; b = In[2 * S + rest]; o = make_float2(0.5f * (a.x + b.x), 0.5f * (a.y + b.y)); }
        else if (e == 0) { a = In[rest]; b = In[3 * S + rest]; o = make_float2(0.5f * (a.x + b.x), 0.5f * (a.y + b.y)); }
        else { a = In[rest]; b = In[3 * S + rest]; o = make_float2(0.5f * (a.x - b.x), 0.5f * (a.y - b.y)); }
        Out[idx] = o;
    }
}

__global__ void __launch_bounds__(1024) amat_kernel(const float* __restrict__ fcw) {
    __shared__ float2 bufA[1024];
    __shared__ float2 bufB[768];
    int tid = threadIdx.x;

    // U into smem: bufA[k*32 + j] = U[k][j]
    bufA[tid] = ((const float2*)g_U)[tid];
    __syncthreads();

    // A_c[s][t] = sum_k d_k Re(conj(U_ks) U_kt), folded with fc_w (full matrix)
    int s = tid >> 5, t = tid & 31;
    float m2 = 0.0f, m3 = 0.0f;
#pragma unroll
    for (int k = 0; k < 32; k++) {
        float2 us = bufA[k * 32 + s];
        float2 ut = bufA[k * 32 + t];
        float pr = us.x * ut.x + us.y * ut.y;
        m2 += ((k >> 2) & 1) ? -pr : pr;   // measured wire 2 (bit pos 2)
        m3 += ((k >> 1) & 1) ? -pr : pr;   // measured wire 3 (bit pos 1)
    }
    float a0 = fcw[0] * m2 + fcw[1] * m3;
    float a1 = fcw[2] * m2 + fcw[3] * m3;

    // scatter to base-4 interleaved index: digit at pos P = 2*s_P + t_P
    int d = 0;
#pragma unroll
    for (int P = 0; P < 5; P++)
        d += ((((s >> P) & 1) * 2 + ((t >> P) & 1)) << (2 * P));
    __syncthreads();
    bufA[d] = make_float2(a0, a1);
    __syncthreads();

    // 5 mode transforms: 1024 -> 768 -> 576 -> 432 -> 324 -> 243
    mode_xform(bufA, bufB, 256); __syncthreads();
    mode_xform(bufB, bufA, 192); __syncthreads();
    mode_xform(bufA, bufB, 144); __syncthreads();
    mode_xform(bufB, bufA, 108); __syncthreads();
    mode_xform(bufA, bufB, 81);  __syncthreads();

    if (tid < 243) g_T[tid] = bufB[tid];
}

// ---------------- kernel 3: per-batch 243-term multilinear form ------------
__global__ void __launch_bounds__(256) qcnn_main(const float* __restrict__ x,
                                                 const float* __restrict__ fcb,
                                                 float2* __restrict__ out, int B) {
    __shared__ u64 sT[243];
    for (int i = threadIdx.x; i < 243; i += 256) sT[i] = ((const u64*)g_T)[i];
    __syncthreads();

    int b = blockIdx.x * 256 + threadIdx.x;
    if (b >= B) return;

    float c[5], s[5];
#pragma unroll
    for (int q = 0; q < 5; q++) sincosf(x[b * 5 + q], &s[q], &c[q]);

    // w = v_{P1} (qubit 3) x v_{P0} (qubit 4), v = (1, cos, sin); w[0]=1 implicit
    u64 w1 = pk(c[4]),        w2 = pk(s[4]);
    u64 w3 = pk(c[3]),        w6 = pk(s[3]);
    u64 w4 = pk(c[3] * c[4]), w5 = pk(c[3] * s[4]);
    u64 w7 = pk(s[3] * c[4]), w8 = pk(s[3] * s[4]);

    u64 r2[27];
#pragma unroll
    for (int j = 0; j < 27; j++) {
        const u64* Tj = sT + j * 9;
        u64 acc = Tj[0];
        acc = f2fma(w1, Tj[1], acc);
        acc = f2fma(w2, Tj[2], acc);
        acc = f2fma(w3, Tj[3], acc);
        acc = f2fma(w4, Tj[4], acc);
        acc = f2fma(w5, Tj[5], acc);
        acc = f2fma(w6, Tj[6], acc);
        acc = f2fma(w7, Tj[7], acc);
        acc = f2fma(w8, Tj[8], acc);
        r2[j] = acc;
    }

    u64 pc2 = pk(c[2]), ps2 = pk(s[2]);
    u64 r1[9];
#pragma unroll
    for (int a = 0; a < 9; a++)
        r1[a] = f2fma(ps2, r2[3 * a + 2], f2fma(pc2, r2[3 * a + 1], r2[3 * a]));

    u64 pc1 = pk(c[1]), ps1 = pk(s[1]);
    u64 r0[3];
#pragma unroll
    for (int a = 0; a < 3; a++)
        r0[a] = f2fma(ps1, r1[3 * a + 2], f2fma(pc1, r1[3 * a + 1], r1[3 * a]));

    u64 rf = f2fma(pk(s[0]), r0[2], f2fma(pk(c[0]), r0[1], r0[0]));
    float o0, o1;
    asm("mov.b64 {%0,%1}, %2;" : "=f"(o0), "=f"(o1) : "l"(rf));

    out[b] = make_float2(o0 + fcb[0], o1 + fcb[1]);
}

extern "C" void kernel_launch(void* const* d_in, const int* in_sizes, int n_in,
                              void* d_out, int out_size) {
    const float* x    = (const float*)d_in[0];  // (B, 5)
    const float* conv = (const float*)d_in[1];  // (2, 15)
    const float* pool = (const float*)d_in[2];  // (2, 2)
    const float* fcw  = (const float*)d_in[3];  // (2, 2)
    const float* fcb  = (const float*)d_in[4];  // (2,)
    float2* out = (float2*)d_out;

    int B = in_sizes[0] / 5;
    sim_kernel<<<32, 32>>>(conv, pool);
    amat_kernel<<<1, 1024>>>(fcw);
    qcnn_main<<<(B + 255) / 256, 256>>>(x, fcb, out, B);
}

// round 3
// speedup vs baseline: 2.6379x; 1.3249x over previous
#include <cuda_runtime.h>

#define SQH 0.70710678118654752440f
typedef unsigned long long u64;

// 243-coeff multilinear tensor, float2 = the two output classes.
// Index: e4*81 + e3*27 + e2*9 + e1*3 + e0, basis {1, cos x_q, sin x_q},
// bit position P = 4 - qubit.
__device__ float2 g_T[243];

// ---------------- f32x2 packed-FMA helpers ---------------------------------
__device__ __forceinline__ u64 pk(float v) {
    u64 r; asm("mov.b64 %0, {%1,%1};" : "=l"(r) : "f"(v)); return r;
}
__device__ __forceinline__ u64 pk2(float a, float b) {
    u64 r; asm("mov.b64 %0, {%1,%2};" : "=l"(r) : "f"(a), "f"(b)); return r;
}
__device__ __forceinline__ u64 f2fma(u64 a, u64 b, u64 c) {
    u64 d; asm("fma.rn.f32x2 %0, %1, %2, %3;" : "=l"(d) : "l"(a), "l"(b), "l"(c));
    return d;
}

// ---------------- warp-level gates: lane l holds amplitude index l ---------
template<int P>
__device__ __forceinline__ void w_rz(int l, float& ar, float& ai, float c, float s) {
    float t = ((l >> P) & 1) ? -s : s;
    float r = ar, i = ai;
    ar = fmaf(t, i, c * r);
    ai = fmaf(-t, r, c * i);
}
// ZZ phase: CNOT(a,b) RZ_b(t) CNOT(a,b) == phase by parity of bits (PA,PB)
template<int PA, int PB>
__device__ __forceinline__ void w_zz(int l, float& ar, float& ai, float c, float s) {
    float t = (((l >> PA) ^ (l >> PB)) & 1) ? -s : s;
    float r = ar, i = ai;
    ar = fmaf(t, i, c * r);
    ai = fmaf(-t, r, c * i);
}
// Constant middle gate M = (RX(-90)xRX(-90)) CNOT (RX(+90)xRX(+90)):
// y = 0.5*[(self + x_b) + sg * i * (x_ab - x_a)], sg = +1 if a_bit==0 else -1
template<int PA, int PB>
__device__ __forceinline__ void w_mid(int l, float& ar, float& ai) {
    float xbr = __shfl_xor_sync(0xffffffffu, ar, 1 << PB);
    float xbi = __shfl_xor_sync(0xffffffffu, ai, 1 << PB);
    float xar = __shfl_xor_sync(0xffffffffu, ar, 1 << PA);
    float xai = __shfl_xor_sync(0xffffffffu, ai, 1 << PA);
    float xdr = __shfl_xor_sync(0xffffffffu, ar, (1 << PA) | (1 << PB));
    float xdi = __shfl_xor_sync(0xffffffffu, ai, (1 << PA) | (1 << PB));
    float s1r = ar + xbr, s1i = ai + xbi;
    float t1r = xdr - xar, t1i = xdi - xai;
    float sg = ((l >> PA) & 1) ? -1.0f : 1.0f;
    ar = 0.5f * fmaf(-sg, t1i, s1r);
    ai = 0.5f * fmaf(sg, t1r, s1i);
}
template<int P>
__device__ __forceinline__ void w_ry(int l, float& ar, float& ai, float c, float sn) {
    float pr = __shfl_xor_sync(0xffffffffu, ar, 1 << P);
    float pi = __shfl_xor_sync(0xffffffffu, ai, 1 << P);
    float sg = ((l >> P) & 1) ? sn : -sn;
    ar = fmaf(sg, pr, c * ar);
    ai = fmaf(sg, pi, c * ai);
}
template<int PC, int PT>
__device__ __forceinline__ void w_cnot(int l, float& ar, float& ai) {
    float pr = __shfl_xor_sync(0xffffffffu, ar, 1 << PT);
    float pi = __shfl_xor_sync(0xffffffffu, ai, 1 << PT);
    if ((l >> PC) & 1) { ar = pr; ai = pi; }
}
template<int PC, int PT>
__device__ __forceinline__ void w_cry(int l, float& ar, float& ai, float c, float sn) {
    float pr = __shfl_xor_sync(0xffffffffu, ar, 1 << PT);
    float pi = __shfl_xor_sync(0xffffffffu, ai, 1 << PT);
    if ((l >> PC) & 1) {
        float sg = ((l >> PT) & 1) ? sn : -sn;
        ar = fmaf(sg, pr, c * ar);
        ai = fmaf(sg, pi, c * ai);
    }
}
template<int PC, int PT>
__device__ __forceinline__ void w_crx(int l, float& ar, float& ai, float c, float sn) {
    float pr = __shfl_xor_sync(0xffffffffu, ar, 1 << PT);
    float pi = __shfl_xor_sync(0xffffffffu, ai, 1 << PT);
    if ((l >> PC) & 1) {
        float r = ar, i = ai;
        ar = fmaf(sn, pi, c * r);
        ai = fmaf(-sn, pr, c * i);
    }
}

// Fused conv iteration: ZZ(t1) -> M -> RZ_b(t2)   (CZ pair cancels exactly)
template<int PA, int PB>
__device__ __forceinline__ void conv_f(int l, float& ar, float& ai, float t1, float t2) {
    float c1, s1, c2, s2;
    sincosf(0.5f * t1, &s1, &c1);
    sincosf(0.5f * t2, &s2, &c2);
    w_zz<PA, PB>(l, ar, ai, c1, s1);
    w_mid<PA, PB>(l, ar, ai);
    w_rz<PB>(l, ar, ai, c2, s2);
}

template<int PA, int PB>
__device__ __forceinline__ void pool_blk(int l, float& ar, float& ai, float w0, float w1) {
    float c0, s0, c1, s1;
    sincosf(0.5f * w0, &s0, &c0);
    sincosf(0.5f * w1, &s1, &c1);
    w_ry<PA>(l, ar, ai, c0, s0);
    w_ry<PB>(l, ar, ai, c1, s1);
    w_cnot<PA, PB>(l, ar, ai);
    w_cry<PB, PA>(l, ar, ai, c0, s0);
    w_crx<PA, PB>(l, ar, ai, c1, s1);
    w_cnot<PB, PA>(l, ar, ai);
}

// ---------------- mode transform: base-4 digit -> 3-basis coefficient ------
__device__ __forceinline__ void mode_xform(const float2* __restrict__ In,
                                           float2* __restrict__ Out, int S) {
    for (int idx = threadIdx.x; idx < 3 * S; idx += 1024) {
        int rest = idx / 3, e = idx - rest * 3;
        float2 a, b, o;
        if (e == 2) { a = In[S + rest]; b = In[2 * S + rest]; o = make_float2(0.5f * (a.x + b.x), 0.5f * (a.y + b.y)); }
        else if (e == 0) { a = In[rest]; b = In[3 * S + rest]; o = make_float2(0.5f * (a.x + b.x), 0.5f * (a.y + b.y)); }
        else { a = In[rest]; b = In[3 * S + rest]; o = make_float2(0.5f * (a.x - b.x), 0.5f * (a.y - b.y)); }
        Out[idx] = o;
    }
}

// ---------------- kernel 1: fused sim (warp j = column j) + amat + xform ---
__global__ void __launch_bounds__(1024) prep_kernel(const float* __restrict__ conv,
                                                    const float* __restrict__ pool,
                                                    const float* __restrict__ fcw) {
    __shared__ float2 bufA[1088];  // U as bufA[j*33 + l]; later base-4 [1024]
    __shared__ float2 bufB[768];
    int tid = threadIdx.x;
    int j = tid >> 5;   // column
    int l = tid & 31;   // amplitude

    float ar = (l == j) ? 1.0f : 0.0f, ai = 0.0f;

    // Layer 0: wires [0..4], pos(w) = 4 - w
    conv_f<4, 3>(l, ar, ai, conv[0], conv[2]);
    conv_f<3, 2>(l, ar, ai, conv[1], conv[3]);
    conv_f<2, 1>(l, ar, ai, conv[2], conv[4]);
    conv_f<1, 0>(l, ar, ai, conv[3], conv[5]);
    conv_f<0, 4>(l, ar, ai, conv[4], conv[6]);
    pool_blk<4, 3>(l, ar, ai, pool[0], pool[1]);
    // Layer 1: wires [1..4]
    conv_f<3, 2>(l, ar, ai, conv[15 + 0], conv[15 + 2]);
    conv_f<2, 1>(l, ar, ai, conv[15 + 1], conv[15 + 3]);
    conv_f<1, 0>(l, ar, ai, conv[15 + 2], conv[15 + 4]);
    conv_f<0, 3>(l, ar, ai, conv[15 + 3], conv[15 + 5]);
    pool_blk<3, 2>(l, ar, ai, pool[2], pool[3]);

    bufA[j * 33 + l] = make_float2(ar, ai);   // U[l][j], conflict-free write
    __syncthreads();

    // A_c[s][t] = sum_k d_k Re(conj(U_ks) U_kt), folded with fc_w
    int s = tid >> 5, t = tid & 31;
    float m2 = 0.0f, m3 = 0.0f;
#pragma unroll
    for (int k = 0; k < 32; k++) {
        float2 us = bufA[s * 33 + k];   // broadcast within warp
        float2 ut = bufA[t * 33 + k];   // 2-way conflict (pad 33)
        float pr = us.x * ut.x + us.y * ut.y;
        m2 += ((k >> 2) & 1) ? -pr : pr;   // measured wire 2 (bit pos 2)
        m3 += ((k >> 1) & 1) ? -pr : pr;   // measured wire 3 (bit pos 1)
    }
    float a0 = fcw[0] * m2 + fcw[1] * m3;
    float a1 = fcw[2] * m2 + fcw[3] * m3;

    // base-4 interleaved index: digit at pos P = 2*s_P + t_P
    int d = 0;
#pragma unroll
    for (int P = 0; P < 5; P++)
        d += ((((s >> P) & 1) * 2 + ((t >> P) & 1)) << (2 * P));
    __syncthreads();
    bufA[d] = make_float2(a0, a1);
    __syncthreads();

    // 5 mode transforms: 1024 -> 768 -> 576 -> 432 -> 324 -> 243
    mode_xform(bufA, bufB, 256); __syncthreads();
    mode_xform(bufB, bufA, 192); __syncthreads();
    mode_xform(bufA, bufB, 144); __syncthreads();
    mode_xform(bufB, bufA, 108); __syncthreads();
    mode_xform(bufA, bufB, 81);  __syncthreads();

    if (tid < 243) g_T[tid] = bufB[tid];
}

// ---------------- kernel 2: per-batch, 2 elements per thread ---------------
__global__ void __launch_bounds__(256) qcnn_main(const float* __restrict__ x,
                                                 const float* __restrict__ fcb,
                                                 float2* __restrict__ out, int B2) {
    __shared__ u64 sT[272];  // 27 rows x 10 u64 (9 used, pad for 16B align)
    for (int i = threadIdx.x; i < 243; i += 256)
        sT[(i / 9) * 10 + (i % 9)] = ((const u64*)g_T)[i];
    __syncthreads();

    int b = blockIdx.x * 256 + threadIdx.x;
    if (b >= B2) return;
    int bb[2] = { b, b + B2 };

    float c[2][5], s[2][5];
#pragma unroll
    for (int e = 0; e < 2; e++)
#pragma unroll
        for (int q = 0; q < 5; q++)
            __sincosf(__ldg(&x[bb[e] * 5 + q]), &s[e][q], &c[e][q]);

    // inner weights (qubits 3,4 -> bit pos 1,0), positions 1..8 of each row
    u64 w[2][8];
    float w2[2][27];
#pragma unroll
    for (int e = 0; e < 2; e++) {
        float c3 = c[e][3], s3 = s[e][3], c4 = c[e][4], s4 = s[e][4];
        w[e][0] = pk(c4);       w[e][1] = pk(s4);
        w[e][2] = pk(c3);       w[e][3] = pk(c3 * c4);
        w[e][4] = pk(c3 * s4);  w[e][5] = pk(s3);
        w[e][6] = pk(s3 * c4);  w[e][7] = pk(s3 * s4);
        float A[3]  = {1.0f, c[e][0], s[e][0]};
        float Bq[3] = {1.0f, c[e][1], s[e][1]};
        float D[3]  = {1.0f, c[e][2], s[e][2]};
#pragma unroll
        for (int e4 = 0; e4 < 3; e4++)
#pragma unroll
            for (int e3 = 0; e3 < 3; e3++) {
                float ab = A[e4] * Bq[e3];
#pragma unroll
                for (int e2 = 0; e2 < 3; e2++)
                    w2[e][e4 * 9 + e3 * 3 + e2] = ab * D[e2];
            }
    }

    u64 bias = pk2(fcb[0], fcb[1]);
    u64 acc0 = bias, acc1 = bias;

#pragma unroll
    for (int jj = 0; jj < 27; jj++) {
        const u64* row = sT + jj * 10;
        ulonglong2 p0 = *(const ulonglong2*)(row + 0);
        ulonglong2 p1 = *(const ulonglong2*)(row + 2);
        ulonglong2 p2 = *(const ulonglong2*)(row + 4);
        ulonglong2 p3 = *(const ulonglong2*)(row + 6);
        u64 p8 = row[8];

        u64 d0 = p0.x;
        d0 = f2fma(w[0][0], p0.y, d0);
        d0 = f2fma(w[0][1], p1.x, d0);
        d0 = f2fma(w[0][2], p1.y, d0);
        d0 = f2fma(w[0][3], p2.x, d0);
        d0 = f2fma(w[0][4], p2.y, d0);
        d0 = f2fma(w[0][5], p3.x, d0);
        d0 = f2fma(w[0][6], p3.y, d0);
        d0 = f2fma(w[0][7], p8,   d0);
        acc0 = f2fma(pk(w2[0][jj]), d0, acc0);

        u64 d1 = p0.x;
        d1 = f2fma(w[1][0], p0.y, d1);
        d1 = f2fma(w[1][1], p1.x, d1);
        d1 = f2fma(w[1][2], p1.y, d1);
        d1 = f2fma(w[1][3], p2.x, d1);
        d1 = f2fma(w[1][4], p2.y, d1);
        d1 = f2fma(w[1][5], p3.x, d1);
        d1 = f2fma(w[1][6], p3.y, d1);
        d1 = f2fma(w[1][7], p8,   d1);
        acc1 = f2fma(pk(w2[1][jj]), d1, acc1);
    }

    float o0, o1, o2, o3;
    asm("mov.b64 {%0,%1}, %2;" : "=f"(o0), "=f"(o1) : "l"(acc0));
    asm("mov.b64 {%0,%1}, %2;" : "=f"(o2), "=f"(o3) : "l"(acc1));
    out[bb[0]] = make_float2(o0, o1);
    out[bb[1]] = make_float2(o2, o3);
}

extern "C" void kernel_launch(void* const* d_in, const int* in_sizes, int n_in,
                              void* d_out, int out_size) {
    const float* x    = (const float*)d_in[0];  // (B, 5)
    const float* conv = (const float*)d_in[1];  // (2, 15)
    const float* pool = (const float*)d_in[2];  // (2, 2)
    const float* fcw  = (const float*)d_in[3];  // (2, 2)
    const float* fcb  = (const float*)d_in[4];  // (2,)
    float2* out = (float2*)d_out;

    int B = in_sizes[0] / 5;
    int B2 = B / 2;
    prep_kernel<<<1, 1024>>>(conv, pool, fcw);
    qcnn_main<<<(B2 + 255) / 256, 256>>>(x, fcb, out, B2);
}